// round 6
// baseline (speedup 1.0000x reference)
#include <cuda_runtime.h>
#include <cuda_bf16.h>
#include <mma.h>
#include <math.h>
#include <stdint.h>

using namespace nvcuda;

#define Bc 8
#define Sc 2048
#define Dc 1024
#define Ec 8
#define SUBD 128
#define SUBH 512
#define SD (Sc*Dc)          // 2097152
#define NCHUNKR 256
#define CHUNKR (SD/NCHUNKR) // 8192

// ---------------- scratch (static device globals) ----------------
// fp32 authoritative path (same as R1)
__device__ float g_h1[16*Sc*SUBH];             // gelu(x_e @ w1 + b1), per (b,k)
__device__ float g_gsel[(long)Bc*Sc*2*SUBH];   // [b][s][k*512+c]
__device__ float g_part[NCHUNKR*Bc*Ec];
__device__ int   g_sel[Bc*2];
// bf16 diagnostic path (outputs unread by authoritative path)
__device__ __align__(16) __nv_bfloat16 g_xh [Bc*Sc*Dc];
__device__ __align__(16) __nv_bfloat16 g_xl [Bc*Sc*Dc];
__device__ __align__(16) __nv_bfloat16 g_h1h[16*Sc*SUBH];
__device__ __align__(16) __nv_bfloat16 g_h1l[16*Sc*SUBH];
__device__ __align__(16) __nv_bfloat16 g_gh [Bc*Sc*Dc];
__device__ __align__(16) __nv_bfloat16 g_gl [Bc*Sc*Dc];
__device__ __align__(16) __nv_bfloat16 g_w1th[Ec*SUBH*SUBD];
__device__ __align__(16) __nv_bfloat16 g_w1tl[Ec*SUBH*SUBD];
__device__ __align__(16) __nv_bfloat16 g_w2th[Ec*SUBH*SUBH];
__device__ __align__(16) __nv_bfloat16 g_w2tl[Ec*SUBH*SUBH];
__device__ __align__(16) __nv_bfloat16 g_woth[Dc*4096];
__device__ __align__(16) __nv_bfloat16 g_wotl[Dc*4096];

__device__ __forceinline__ float gelu_exact(float v) {
    return 0.5f * v * (1.0f + erff(v * 0.70710678118654752440f));
}

// ============================================================
// Routing stage 1 (R1 verbatim — proven)
// ============================================================
__global__ void route_partial_kernel(const float* __restrict__ x,
                                     const float* __restrict__ w) {
    const int chunk = blockIdx.x;
    const int tid   = threadIdx.x;

    float acc[Bc][Ec];
#pragma unroll
    for (int b = 0; b < Bc; b++)
#pragma unroll
        for (int e = 0; e < Ec; e++) acc[b][e] = 0.f;

    const long base = (long)chunk * CHUNKR;
    for (int it = 0; it < CHUNKR / 256; it++) {
        const long i = base + it * 256 + tid;
        const float4 w0 = *(const float4*)(w + i * 8);
        const float4 w1v = *(const float4*)(w + i * 8 + 4);
        const float wv[8] = {w0.x, w0.y, w0.z, w0.w, w1v.x, w1v.y, w1v.z, w1v.w};
#pragma unroll
        for (int b = 0; b < Bc; b++) {
            const float xv = x[(long)b * SD + i];
#pragma unroll
            for (int e = 0; e < Ec; e++) acc[b][e] = fmaf(xv, wv[e], acc[b][e]);
        }
    }

    __shared__ float sm[8][64];
    const int lane = tid & 31, warp = tid >> 5;
#pragma unroll
    for (int b = 0; b < Bc; b++) {
#pragma unroll
        for (int e = 0; e < Ec; e++) {
            float v = acc[b][e];
#pragma unroll
            for (int o = 16; o > 0; o >>= 1) v += __shfl_down_sync(0xffffffffu, v, o);
            if (lane == 0) sm[warp][b * 8 + e] = v;
        }
    }
    __syncthreads();
    if (tid < 64) {
        float s = 0.f;
#pragma unroll
        for (int w2 = 0; w2 < 8; w2++) s += sm[w2][tid];
        g_part[chunk * 64 + tid] = s;
    }
}

// ============================================================
// Routing stage 2 (R1 verbatim — proven)
// ============================================================
__global__ void route_topk_kernel(const float* __restrict__ b_switch) {
    __shared__ float lg[64];
    const int t = threadIdx.x;
    float s = b_switch[t & 7];
    for (int c = 0; c < NCHUNKR; c++) s += g_part[c * 64 + t];
    lg[t] = s;
    __syncthreads();
    if (t < Bc) {
        const float* L = lg + t * 8;
        int i0 = 0; float v0 = L[0];
#pragma unroll
        for (int e = 1; e < 8; e++) if (L[e] > v0) { v0 = L[e]; i0 = e; }
        int i1 = -1; float v1 = -3.0e38f;
#pragma unroll
        for (int e = 0; e < 8; e++) if (e != i0 && L[e] > v1) { v1 = L[e]; i1 = e; }
        g_sel[t * 2 + 0] = i0;
        g_sel[t * 2 + 1] = i1;
    }
}

// ============================================================
// DIAGNOSTIC: x -> bf16 hi/lo (output unread by authoritative path)
// ============================================================
__global__ void convert_x_kernel(const float4* __restrict__ x) {
    const size_t i = (size_t)blockIdx.x * blockDim.x + threadIdx.x;
    const float4 v = x[i];
    __nv_bfloat16 h0 = __float2bfloat16(v.x), h1 = __float2bfloat16(v.y);
    __nv_bfloat16 h2 = __float2bfloat16(v.z), h3 = __float2bfloat16(v.w);
    __nv_bfloat162 hi01; hi01.x = h0; hi01.y = h1;
    __nv_bfloat162 hi23; hi23.x = h2; hi23.y = h3;
    __nv_bfloat162 lo01, lo23;
    lo01.x = __float2bfloat16(v.x - __bfloat162float(h0));
    lo01.y = __float2bfloat16(v.y - __bfloat162float(h1));
    lo23.x = __float2bfloat16(v.z - __bfloat162float(h2));
    lo23.y = __float2bfloat16(v.w - __bfloat162float(h3));
    ((__nv_bfloat162*)g_xh)[i * 2]     = hi01;
    ((__nv_bfloat162*)g_xh)[i * 2 + 1] = hi23;
    ((__nv_bfloat162*)g_xl)[i * 2]     = lo01;
    ((__nv_bfloat162*)g_xl)[i * 2 + 1] = lo23;
}

// ============================================================
// DIAGNOSTIC: weight [K][N] fp32 -> [N][K] bf16 hi/lo
// ============================================================
__global__ void transpose_split_kernel(const float* __restrict__ in,
                                       __nv_bfloat16* __restrict__ hi,
                                       __nv_bfloat16* __restrict__ lo,
                                       int K, int N) {
    __shared__ float t[32][33];
    const size_t moff = (size_t)blockIdx.z * K * N;
    const int n0 = blockIdx.x * 32, k0 = blockIdx.y * 32;
    const int tx = threadIdx.x, ty = threadIdx.y;
#pragma unroll
    for (int i = 0; i < 32; i += 8)
        t[ty + i][tx] = in[moff + (size_t)(k0 + ty + i) * N + n0 + tx];
    __syncthreads();
#pragma unroll
    for (int i = 0; i < 32; i += 8) {
        const float v = t[tx][ty + i];
        const __nv_bfloat16 h = __float2bfloat16(v);
        const size_t o = moff + (size_t)(n0 + ty + i) * K + k0 + tx;
        hi[o] = h;
        lo[o] = __float2bfloat16(v - __bfloat162float(h));
    }
}

// ============================================================
// DIAGNOSTIC: R5 WMMA kernel (MODE 0 only), output to dummy scratch.
// ============================================================
#define ROWE 80
#define PAIRE (128*ROWE)
#define STAGEE (2*PAIRE)

template <int MODE>
__global__ void __launch_bounds__(256)
wmma_gemm(const float* __restrict__ bias0, float* __restrict__ outp) {
    extern __shared__ __nv_bfloat16 smem[];

    const int tid = threadIdx.x;
    const int z = blockIdx.z;
    const int rowBlock = blockIdx.y * 128;
    const int colBlock = blockIdx.x * 128;
    const int warp = tid >> 5, lane = tid & 31;
    const int wm = warp & 3, wn = warp >> 2;

    const __nv_bfloat16 *aH, *aL, *bH, *bL;
    const float* bias;
    int lda, ldb, akbase, nstages, e0 = 0, e1 = 0;
    if (MODE == 0) {
        const int e = g_sel[z];
        aH = g_xh + (size_t)(z >> 1) * Sc * Dc;
        aL = g_xl + (size_t)(z >> 1) * Sc * Dc;
        lda = Dc; akbase = e * SUBD;
        bH = g_w1th + (size_t)e * SUBH * SUBD;
        bL = g_w1tl + (size_t)e * SUBH * SUBD;
        ldb = SUBD;
        bias = bias0 + e * SUBH;
        nstages = SUBD / 32;
    } else if (MODE == 1) {
        const int e = g_sel[z];
        aH = g_h1h + (size_t)z * Sc * SUBH;
        aL = g_h1l + (size_t)z * Sc * SUBH;
        lda = SUBH; akbase = 0;
        bH = g_w2th + (size_t)e * SUBH * SUBH;
        bL = g_w2tl + (size_t)e * SUBH * SUBH;
        ldb = SUBH;
        bias = bias0 + e * SUBH;
        nstages = SUBH / 32;
    } else {
        aH = g_gh + (size_t)z * Sc * Dc;
        aL = g_gl + (size_t)z * Sc * Dc;
        lda = Dc; akbase = 0;
        bH = g_woth; bL = g_wotl;
        ldb = 4096;
        bias = bias0;
        nstages = Dc / 32;
        e0 = g_sel[z * 2]; e1 = g_sel[z * 2 + 1];
    }

    wmma::fragment<wmma::accumulator, 16, 16, 16, float> acc[2][4];
#pragma unroll
    for (int mt = 0; mt < 2; mt++)
#pragma unroll
        for (int nt = 0; nt < 4; nt++) wmma::fill_fragment(acc[mt][nt], 0.0f);

    for (int c = 0; c < nstages; c++) {
        __syncthreads();
        const int ak0 = akbase + c * 32;
        int bk0;
        if (MODE == 2) {
            const int kg = c * 32;
            bk0 = (kg < SUBH) ? (e0 * SUBH + kg) : (e1 * SUBH + kg - SUBH);
        } else bk0 = c * 32;
#pragma unroll
        for (int j = 0; j < 8; j++) {
            const int s2 = tid + j * 256;
            const int pairI = s2 >> 10;
            const int p = s2 & 1023;
            const int row = p >> 3, q = p & 7;
            const uint32_t dstE = (uint32_t)pairI * PAIRE
                                + (uint32_t)(row * ROWE + (q & 3) * 8 + (q >> 2) * 32);
            const __nv_bfloat16* src;
            if (pairI == 0) {
                const size_t off = (size_t)(rowBlock + row) * lda + ak0 + (q & 3) * 8;
                src = ((q >> 2) == 0 ? aH : aL) + off;
            } else {
                const size_t off = (size_t)(colBlock + row) * ldb + bk0 + (q & 3) * 8;
                src = ((q >> 2) == 0 ? bH : bL) + off;
            }
            *(uint4*)(smem + dstE) = *(const uint4*)src;
        }
        __syncthreads();

#pragma unroll
        for (int kk = 0; kk < 2; kk++) {
            wmma::fragment<wmma::matrix_a, 16, 16, 16, __nv_bfloat16, wmma::row_major> ah[2], al[2];
#pragma unroll
            for (int mt = 0; mt < 2; mt++) {
                const __nv_bfloat16* ab = smem + (wm * 32 + mt * 16) * ROWE + kk * 16;
                wmma::load_matrix_sync(ah[mt], ab, ROWE);
                wmma::load_matrix_sync(al[mt], ab + 32, ROWE);
            }
#pragma unroll
            for (int nt = 0; nt < 4; nt++) {
                wmma::fragment<wmma::matrix_b, 16, 16, 16, __nv_bfloat16, wmma::col_major> bh, bl;
                const __nv_bfloat16* bb = smem + PAIRE + (wn * 64 + nt * 16) * ROWE + kk * 16;
                wmma::load_matrix_sync(bh, bb, ROWE);
                wmma::load_matrix_sync(bl, bb + 32, ROWE);
#pragma unroll
                for (int mt = 0; mt < 2; mt++) {
                    wmma::mma_sync(acc[mt][nt], ah[mt], bh, acc[mt][nt]);
                    wmma::mma_sync(acc[mt][nt], ah[mt], bl, acc[mt][nt]);
                    wmma::mma_sync(acc[mt][nt], al[mt], bh, acc[mt][nt]);
                }
            }
        }
    }

    __syncthreads();
    float* scr = (float*)smem + warp * (16 * 68);
    const int srow = lane >> 1;
    const int cb = (lane & 1) * 32;

#pragma unroll
    for (int mt = 0; mt < 2; mt++) {
#pragma unroll
        for (int nt = 0; nt < 4; nt++)
            wmma::store_matrix_sync(scr + nt * 16, acc[mt][nt], 68, wmma::mem_row_major);
        __syncwarp();

        const int grow = rowBlock + wm * 32 + mt * 16 + srow;
        const int gcol0 = colBlock + wn * 64 + cb;

        if (MODE == 2) {
            float* orow = outp + (size_t)(z * Sc + grow) * Dc + gcol0;
#pragma unroll
            for (int cc = 0; cc < 32; cc += 2) {
                const float v0 = scr[srow * 68 + cb + cc]     + bias[gcol0 + cc];
                const float v1 = scr[srow * 68 + cb + cc + 1] + bias[gcol0 + cc + 1];
                *(float2*)(orow + cc) = make_float2(v0, v1);
            }
        } else {
            size_t o;
            __nv_bfloat16 *hD, *lD;
            if (MODE == 0) {
                o = (size_t)(z * Sc + grow) * SUBH + gcol0;
                hD = g_h1h; lD = g_h1l;
            } else {
                o = (size_t)((z >> 1) * Sc + grow) * Dc + (z & 1) * SUBH + gcol0;
                hD = g_gh; lD = g_gl;
            }
#pragma unroll
            for (int cc = 0; cc < 32; cc += 2) {
                const float g0 = gelu_exact(scr[srow * 68 + cb + cc]     + bias[gcol0 + cc]);
                const float g1 = gelu_exact(scr[srow * 68 + cb + cc + 1] + bias[gcol0 + cc + 1]);
                const __nv_bfloat16 h0 = __float2bfloat16(g0);
                const __nv_bfloat16 h1 = __float2bfloat16(g1);
                __nv_bfloat162 hp; hp.x = h0; hp.y = h1;
                __nv_bfloat162 lp;
                lp.x = __float2bfloat16(g0 - __bfloat162float(h0));
                lp.y = __float2bfloat16(g1 - __bfloat162float(h1));
                *(__nv_bfloat162*)(hD + o + cc) = hp;
                *(__nv_bfloat162*)(lD + o + cc) = lp;
            }
        }
        __syncwarp();
    }
}

// ============================================================
// AUTHORITATIVE fp32 tiled GEMM (R1-derived), BK 8 -> 16
// MODE 0: h1 = gelu(x[:, e*128:+128] @ w1[e] + b1[e])        (K=128)
// MODE 1: g  = gelu(h1 @ w2[e] + b2[e])                      (K=512)
// MODE 2: out = g_cat @ gather(w_out) + b_out                (K=1024)
// ============================================================
template <int MODE, bool DO_GELU>
__global__ void __launch_bounds__(256, 2)
gemm_kernel(const float* __restrict__ A0, const float* __restrict__ B0,
            const float* __restrict__ bias0, float* __restrict__ C0) {
    constexpr int BM = 128, BN = 128, BK = 16, TM = 8, TN = 8;
    __shared__ float As[BK][BM];
    __shared__ float Bs[BK][BN];

    const int z   = blockIdx.z;
    const int tid = threadIdx.x;
    const int tx  = tid & 15, ty = tid >> 4;
    const int rowBlock = blockIdx.y * BM;
    const int colBlock = blockIdx.x * BN;

    const float* A; const float* bias; float* C;
    int lda, ldc, Kdim;
    int e0 = 0, e1 = 0;
    const float* Bbase = B0;

    if (MODE == 0) {
        const int e = g_sel[z];
        A = A0 + (long)(z >> 1) * SD + e * SUBD; lda = Dc; Kdim = SUBD;
        Bbase = B0 + (long)e * SUBD * SUBH;
        bias = bias0 + e * SUBH;
        C = g_h1 + (long)z * Sc * SUBH; ldc = SUBH;
    } else if (MODE == 1) {
        const int e = g_sel[z];
        A = g_h1 + (long)z * Sc * SUBH; lda = SUBH; Kdim = SUBH;
        Bbase = B0 + (long)e * SUBH * SUBH;
        bias = bias0 + e * SUBH;
        C = g_gsel + (long)(z >> 1) * Sc * (2 * SUBH) + (z & 1) * SUBH; ldc = 2 * SUBH;
    } else {
        A = g_gsel + (long)z * Sc * (2 * SUBH); lda = 2 * SUBH; Kdim = 2 * SUBH;
        bias = bias0;
        C = C0 + (long)z * Sc * Dc; ldc = Dc;
        e0 = g_sel[z * 2]; e1 = g_sel[z * 2 + 1];
    }

    float acc[TM][TN];
#pragma unroll
    for (int i = 0; i < TM; i++)
#pragma unroll
        for (int j = 0; j < TN; j++) acc[i][j] = 0.f;

    const int arow = tid >> 1, acol = (tid & 1) * 4;   // A: 128 rows, k acol & acol+8
    const int brow = tid >> 5, bcol = (tid & 31) * 4;  // B: k rows brow & brow+8

    for (int k0 = 0; k0 < Kdim; k0 += BK) {
        // A tile: two float4 per thread, transposed into smem
        const float* Ar = A + (long)(rowBlock + arow) * lda + k0 + acol;
        const float4 av0 = *(const float4*)(Ar);
        const float4 av1 = *(const float4*)(Ar + 8);
        As[acol + 0][arow] = av0.x;
        As[acol + 1][arow] = av0.y;
        As[acol + 2][arow] = av0.z;
        As[acol + 3][arow] = av0.w;
        As[acol + 8][arow] = av1.x;
        As[acol + 9][arow] = av1.y;
        As[acol + 10][arow] = av1.z;
        As[acol + 11][arow] = av1.w;

        // B tile: rows brow and brow+8
#pragma unroll
        for (int bb = 0; bb < 2; bb++) {
            const int kk = k0 + brow + bb * 8;
            const float* Brow;
            if (MODE == 2) {
                const int r = (kk < SUBH) ? (e0 * SUBH + kk) : (e1 * SUBH + kk - SUBH);
                Brow = B0 + (long)r * Dc;
            } else {
                Brow = Bbase + (long)kk * SUBH;
            }
            *(float4*)(&Bs[brow + bb * 8][bcol]) = *(const float4*)(Brow + colBlock + bcol);
        }
        __syncthreads();

#pragma unroll
        for (int k = 0; k < BK; k++) {
            float a[TM], bv[TN];
            const float4 a0 = *(const float4*)(&As[k][ty * TM]);
            const float4 a1 = *(const float4*)(&As[k][ty * TM + 4]);
            a[0]=a0.x; a[1]=a0.y; a[2]=a0.z; a[3]=a0.w;
            a[4]=a1.x; a[5]=a1.y; a[6]=a1.z; a[7]=a1.w;
            const float4 b0v = *(const float4*)(&Bs[k][tx * TN]);
            const float4 b1v = *(const float4*)(&Bs[k][tx * TN + 4]);
            bv[0]=b0v.x; bv[1]=b0v.y; bv[2]=b0v.z; bv[3]=b0v.w;
            bv[4]=b1v.x; bv[5]=b1v.y; bv[6]=b1v.z; bv[7]=b1v.w;
#pragma unroll
            for (int i = 0; i < TM; i++)
#pragma unroll
                for (int j = 0; j < TN; j++)
                    acc[i][j] = fmaf(a[i], bv[j], acc[i][j]);
        }
        __syncthreads();
    }

    // epilogue: + bias, optional gelu, vectorized store (R1 verbatim)
    const int crow0 = rowBlock + ty * TM;
    const int ccol0 = colBlock + tx * TN;
    float bv[TN];
#pragma unroll
    for (int j = 0; j < TN; j++) bv[j] = bias[ccol0 + j];
#pragma unroll
    for (int i = 0; i < TM; i++) {
        float v[TN];
#pragma unroll
        for (int j = 0; j < TN; j++) {
            float t = acc[i][j] + bv[j];
            v[j] = DO_GELU ? gelu_exact(t) : t;
        }
        float* cp = C + (long)(crow0 + i) * ldc + ccol0;
        *(float4*)(cp)     = make_float4(v[0], v[1], v[2], v[3]);
        *(float4*)(cp + 4) = make_float4(v[4], v[5], v[6], v[7]);
    }
}

// ============================================================
extern "C" void kernel_launch(void* const* d_in, const int* in_sizes, int n_in,
                              void* d_out, int out_size) {
    const float* x        = (const float*)d_in[0];
    const float* w_switch = (const float*)d_in[1];
    const float* b_switch = (const float*)d_in[2];
    const float* w1       = (const float*)d_in[3];
    const float* b1       = (const float*)d_in[4];
    const float* w2       = (const float*)d_in[5];
    const float* b2       = (const float*)d_in[6];
    const float* w_out    = (const float*)d_in[7];
    const float* b_out    = (const float*)d_in[8];
    float* out = (float*)d_out;

    // 1) routing (proven)
    route_partial_kernel<<<NCHUNKR, 256>>>(x, w_switch);
    route_topk_kernel<<<1, 64>>>(b_switch);

    // 2) DIAGNOSTICS (outputs unread by authoritative path)
    convert_x_kernel<<<(Bc * Sc * Dc / 4) / 256, 256>>>((const float4*)x);
    transpose_split_kernel<<<dim3(SUBH / 32, SUBD / 32, Ec), dim3(32, 8)>>>(w1, g_w1th, g_w1tl, SUBD, SUBH);
    transpose_split_kernel<<<dim3(SUBH / 32, SUBH / 32, Ec), dim3(32, 8)>>>(w2, g_w2th, g_w2tl, SUBH, SUBH);
    transpose_split_kernel<<<dim3(Dc / 32, 4096 / 32, 1), dim3(32, 8)>>>(w_out, g_woth, g_wotl, 4096, Dc);
    wmma_gemm<0><<<dim3(SUBH / 128, Sc / 128, 16), 256, STAGEE * 2>>>(b1, nullptr);

    // 3) AUTHORITATIVE fp32 pipeline (R1-derived, BK=16) -> d_out
    gemm_kernel<0, true><<<dim3(SUBH / 128, Sc / 128, 16), 256>>>(x, w1, b1, nullptr);
    gemm_kernel<1, true><<<dim3(SUBH / 128, Sc / 128, 16), 256>>>(nullptr, w2, b2, nullptr);
    gemm_kernel<2, false><<<dim3(Dc / 128, Sc / 128, Bc), 256>>>(nullptr, w_out, b_out, out);
}

// round 8
// speedup vs baseline: 1.1478x; 1.1478x over previous
#include <cuda_runtime.h>
#include <cuda_bf16.h>
#include <mma.h>
#include <math.h>
#include <stdint.h>

using namespace nvcuda;

#define Bc 8
#define Sc 2048
#define Dc 1024
#define Ec 8
#define SUBD 128
#define SUBH 512
#define SD (Sc*Dc)          // 2097152
#define NCHUNKR 256
#define CHUNKR (SD/NCHUNKR) // 8192

// ---------------- scratch (static device globals) ----------------
__device__ float g_h1[16*Sc*SUBH];             // fp32 h1
__device__ float g_gsel[(long)Bc*Sc*2*SUBH];   // fp32 concat g
__device__ float g_part[NCHUNKR*Bc*Ec];
__device__ int   g_sel[Bc*2];

__device__ __forceinline__ float gelu_exact(float v) {
    return 0.5f * v * (1.0f + erff(v * 0.70710678118654752440f));
}

// ============================================================
// Routing stage 1 (R1 verbatim — proven)
// ============================================================
__global__ void route_partial_kernel(const float* __restrict__ x,
                                     const float* __restrict__ w) {
    const int chunk = blockIdx.x;
    const int tid   = threadIdx.x;

    float acc[Bc][Ec];
#pragma unroll
    for (int b = 0; b < Bc; b++)
#pragma unroll
        for (int e = 0; e < Ec; e++) acc[b][e] = 0.f;

    const long base = (long)chunk * CHUNKR;
    for (int it = 0; it < CHUNKR / 256; it++) {
        const long i = base + it * 256 + tid;
        const float4 w0 = *(const float4*)(w + i * 8);
        const float4 w1v = *(const float4*)(w + i * 8 + 4);
        const float wv[8] = {w0.x, w0.y, w0.z, w0.w, w1v.x, w1v.y, w1v.z, w1v.w};
#pragma unroll
        for (int b = 0; b < Bc; b++) {
            const float xv = x[(long)b * SD + i];
#pragma unroll
            for (int e = 0; e < Ec; e++) acc[b][e] = fmaf(xv, wv[e], acc[b][e]);
        }
    }

    __shared__ float sm[8][64];
    const int lane = tid & 31, warp = tid >> 5;
#pragma unroll
    for (int b = 0; b < Bc; b++) {
#pragma unroll
        for (int e = 0; e < Ec; e++) {
            float v = acc[b][e];
#pragma unroll
            for (int o = 16; o > 0; o >>= 1) v += __shfl_down_sync(0xffffffffu, v, o);
            if (lane == 0) sm[warp][b * 8 + e] = v;
        }
    }
    __syncthreads();
    if (tid < 64) {
        float s = 0.f;
#pragma unroll
        for (int w2 = 0; w2 < 8; w2++) s += sm[w2][tid];
        g_part[chunk * 64 + tid] = s;
    }
}

// ============================================================
// Routing stage 2 (R1 verbatim — proven)
// ============================================================
__global__ void route_topk_kernel(const float* __restrict__ b_switch) {
    __shared__ float lg[64];
    const int t = threadIdx.x;
    float s = b_switch[t & 7];
    for (int c = 0; c < NCHUNKR; c++) s += g_part[c * 64 + t];
    lg[t] = s;
    __syncthreads();
    if (t < Bc) {
        const float* L = lg + t * 8;
        int i0 = 0; float v0 = L[0];
#pragma unroll
        for (int e = 1; e < 8; e++) if (L[e] > v0) { v0 = L[e]; i0 = e; }
        int i1 = -1; float v1 = -3.0e38f;
#pragma unroll
        for (int e = 0; e < 8; e++) if (e != i0 && L[e] > v1) { v1 = L[e]; i1 = e; }
        g_sel[t * 2 + 0] = i0;
        g_sel[t * 2 + 1] = i1;
    }
}

// ============================================================
// WMMA 3xBF16-split GEMM with IN-KERNEL fp32->bf16 hi/lo conversion.
// No pre-converted buffers: reads fp32 activations and fp32 row-major
// [K][N] weights straight from proven-good sources.
// CTA tile 128x128, 8 warps (4x2) each 32x64, BK=32, single stage.
// smem row = [hi 32 elems][lo 32 elems][pad 16] = 80 elems (160B).
// MODE 0: g_h1  = gelu(x[:, e*128:+128] @ w1[e] + b1[e])   K=128
// MODE 1: g_gsel= gelu(g_h1 @ w2[e] + b2[e])               K=512
// MODE 2: out   = g_gsel @ gather(w_out) + b_out           K=1024
// ============================================================
#define ROWE 80
#define PAIRE (128*ROWE)
#define STAGEE (2*PAIRE)     // 20480 elems = 40960 bytes

template <int MODE>
__global__ void __launch_bounds__(256)
conv_wmma_gemm(const float* __restrict__ A0, const float* __restrict__ B0,
               const float* __restrict__ bias0, float* __restrict__ outp) {
    extern __shared__ __nv_bfloat16 smem[];

    const int tid = threadIdx.x;
    const int z = blockIdx.z;
    const int rowBlock = blockIdx.y * 128;
    const int colBlock = blockIdx.x * 128;
    const int warp = tid >> 5, lane = tid & 31;
    const int wm = warp & 3, wn = warp >> 2;

    const float* A;
    const float* Bp;
    const float* bias;
    int lda, ldn, akbase, nstages, e0 = 0, e1 = 0;
    if (MODE == 0) {
        const int e = g_sel[z];
        A = A0 + (size_t)(z >> 1) * SD; lda = Dc; akbase = e * SUBD;
        Bp = B0 + (size_t)e * SUBD * SUBH; ldn = SUBH;
        bias = bias0 + e * SUBH;
        nstages = SUBD / 32;
    } else if (MODE == 1) {
        const int e = g_sel[z];
        A = g_h1 + (size_t)z * Sc * SUBH; lda = SUBH; akbase = 0;
        Bp = B0 + (size_t)e * SUBH * SUBH; ldn = SUBH;
        bias = bias0 + e * SUBH;
        nstages = SUBH / 32;
    } else {
        A = g_gsel + (size_t)z * Sc * (2 * SUBH); lda = 2 * SUBH; akbase = 0;
        Bp = B0; ldn = Dc;
        bias = bias0;
        nstages = (2 * SUBH) / 32;
        e0 = g_sel[z * 2]; e1 = g_sel[z * 2 + 1];
    }

    wmma::fragment<wmma::accumulator, 16, 16, 16, float> acc[2][4];
#pragma unroll
    for (int mt = 0; mt < 2; mt++)
#pragma unroll
        for (int nt = 0; nt < 4; nt++) wmma::fill_fragment(acc[mt][nt], 0.0f);

    for (int c = 0; c < nstages; c++) {
        __syncthreads();
        const int ak0 = akbase + c * 32;
        const int bk0 = c * 32;

        // ---- stage A: 128 rows x 32 k, fp32 -> bf16 hi/lo in smem ----
#pragma unroll
        for (int j = 0; j < 16; j++) {
            const int idx = tid + j * 256;        // 0..4095
            const int m = idx >> 5, k = idx & 31;
            const float f = A[(size_t)(rowBlock + m) * lda + ak0 + k];
            const __nv_bfloat16 h = __float2bfloat16(f);
            smem[m * ROWE + k]      = h;
            smem[m * ROWE + 32 + k] = __float2bfloat16(f - __bfloat162float(h));
        }
        // ---- stage B: 32 k x 128 n (row-major [K][N] weights) ----
#pragma unroll
        for (int j = 0; j < 16; j++) {
            const int idx = tid + j * 256;        // 0..4095
            const int k = idx >> 7, n = idx & 127;
            const int kg = bk0 + k;
            const float* brow;
            if (MODE == 2) {
                const int r = (kg < SUBH) ? (e0 * SUBH + kg) : (e1 * SUBH + kg - SUBH);
                brow = Bp + (size_t)r * Dc;
            } else {
                brow = Bp + (size_t)kg * ldn;
            }
            const float f = brow[colBlock + n];
            const __nv_bfloat16 h = __float2bfloat16(f);
            smem[PAIRE + n * ROWE + k]      = h;
            smem[PAIRE + n * ROWE + 32 + k] = __float2bfloat16(f - __bfloat162float(h));
        }
        __syncthreads();

        // ---- compute (identical to R6/R7 core) ----
#pragma unroll
        for (int kk = 0; kk < 2; kk++) {
            wmma::fragment<wmma::matrix_a, 16, 16, 16, __nv_bfloat16, wmma::row_major> ah[2], al[2];
#pragma unroll
            for (int mt = 0; mt < 2; mt++) {
                const __nv_bfloat16* ab = smem + (wm * 32 + mt * 16) * ROWE + kk * 16;
                wmma::load_matrix_sync(ah[mt], ab, ROWE);
                wmma::load_matrix_sync(al[mt], ab + 32, ROWE);
            }
#pragma unroll
            for (int nt = 0; nt < 4; nt++) {
                wmma::fragment<wmma::matrix_b, 16, 16, 16, __nv_bfloat16, wmma::col_major> bh, bl;
                const __nv_bfloat16* bb = smem + PAIRE + (wn * 64 + nt * 16) * ROWE + kk * 16;
                wmma::load_matrix_sync(bh, bb, ROWE);
                wmma::load_matrix_sync(bl, bb + 32, ROWE);
#pragma unroll
                for (int mt = 0; mt < 2; mt++) {
                    wmma::mma_sync(acc[mt][nt], ah[mt], bh, acc[mt][nt]);
                    wmma::mma_sync(acc[mt][nt], ah[mt], bl, acc[mt][nt]);
                    wmma::mma_sync(acc[mt][nt], al[mt], bh, acc[mt][nt]);
                }
            }
        }
    }

    // ---- epilogue: store frags to per-warp smem scratch, transform, write ----
    __syncthreads();
    float* scr = (float*)smem + warp * (16 * 68);
    const int srow = lane >> 1;
    const int cb = (lane & 1) * 32;

#pragma unroll
    for (int mt = 0; mt < 2; mt++) {
#pragma unroll
        for (int nt = 0; nt < 4; nt++)
            wmma::store_matrix_sync(scr + nt * 16, acc[mt][nt], 68, wmma::mem_row_major);
        __syncwarp();

        const int grow = rowBlock + wm * 32 + mt * 16 + srow;
        const int gcol0 = colBlock + wn * 64 + cb;

        if (MODE == 2) {
            float* orow = outp + (size_t)(z * Sc + grow) * Dc + gcol0;
#pragma unroll
            for (int cc = 0; cc < 32; cc += 2) {
                const float v0 = scr[srow * 68 + cb + cc]     + bias[gcol0 + cc];
                const float v1 = scr[srow * 68 + cb + cc + 1] + bias[gcol0 + cc + 1];
                *(float2*)(orow + cc) = make_float2(v0, v1);
            }
        } else {
            float* dst;
            if (MODE == 0) {
                dst = g_h1 + (size_t)(z * Sc + grow) * SUBH + gcol0;
            } else {
                dst = g_gsel + (size_t)((z >> 1) * Sc + grow) * (2 * SUBH)
                    + (z & 1) * SUBH + gcol0;
            }
#pragma unroll
            for (int cc = 0; cc < 32; cc += 2) {
                const float g0 = gelu_exact(scr[srow * 68 + cb + cc]     + bias[gcol0 + cc]);
                const float g1 = gelu_exact(scr[srow * 68 + cb + cc + 1] + bias[gcol0 + cc + 1]);
                *(float2*)(dst + cc) = make_float2(g0, g1);
            }
        }
        __syncwarp();
    }
}

// ============================================================
extern "C" void kernel_launch(void* const* d_in, const int* in_sizes, int n_in,
                              void* d_out, int out_size) {
    const float* x        = (const float*)d_in[0];
    const float* w_switch = (const float*)d_in[1];
    const float* b_switch = (const float*)d_in[2];
    const float* w1       = (const float*)d_in[3];
    const float* b1       = (const float*)d_in[4];
    const float* w2       = (const float*)d_in[5];
    const float* b2       = (const float*)d_in[6];
    const float* w_out    = (const float*)d_in[7];
    const float* b_out    = (const float*)d_in[8];
    float* out = (float*)d_out;

    const int SMEM = STAGEE * 2;   // 40960 bytes, under 48KB default

    // 1) routing (proven)
    route_partial_kernel<<<NCHUNKR, 256>>>(x, w_switch);
    route_topk_kernel<<<1, 64>>>(b_switch);

    // 2) WMMA expert MLP with in-kernel conversion (no pre-pass buffers)
    conv_wmma_gemm<0><<<dim3(SUBH / 128, Sc / 128, 16), 256, SMEM>>>(x, w1, b1, nullptr);
    conv_wmma_gemm<1><<<dim3(SUBH / 128, Sc / 128, 16), 256, SMEM>>>(nullptr, w2, b2, nullptr);
    conv_wmma_gemm<2><<<dim3(Dc / 128, Sc / 128, Bc), 256, SMEM>>>(nullptr, w_out, b_out, out);
}

// round 9
// speedup vs baseline: 2.0252x; 1.7644x over previous
#include <cuda_runtime.h>
#include <cuda_bf16.h>
#include <mma.h>
#include <math.h>
#include <stdint.h>

using namespace nvcuda;

#define Bc 8
#define Sc 2048
#define Dc 1024
#define Ec 8
#define SUBD 128
#define SUBH 512
#define SD (Sc*Dc)
#define NCHUNKR 256
#define CHUNKR (SD/NCHUNKR)

// ---------------- scratch (static device globals) ----------------
__device__ float g_h1[16*Sc*SUBH];
__device__ float g_gsel[(long)Bc*Sc*2*SUBH];
__device__ float g_part[NCHUNKR*Bc*Ec];
__device__ int   g_sel[Bc*2];

__device__ __forceinline__ float gelu_exact(float v) {
    return 0.5f * v * (1.0f + erff(v * 0.70710678118654752440f));
}

// ============================================================
// Routing (R1 verbatim — proven)
// ============================================================
__global__ void route_partial_kernel(const float* __restrict__ x,
                                     const float* __restrict__ w) {
    const int chunk = blockIdx.x;
    const int tid   = threadIdx.x;

    float acc[Bc][Ec];
#pragma unroll
    for (int b = 0; b < Bc; b++)
#pragma unroll
        for (int e = 0; e < Ec; e++) acc[b][e] = 0.f;

    const long base = (long)chunk * CHUNKR;
    for (int it = 0; it < CHUNKR / 256; it++) {
        const long i = base + it * 256 + tid;
        const float4 w0 = *(const float4*)(w + i * 8);
        const float4 w1v = *(const float4*)(w + i * 8 + 4);
        const float wv[8] = {w0.x, w0.y, w0.z, w0.w, w1v.x, w1v.y, w1v.z, w1v.w};
#pragma unroll
        for (int b = 0; b < Bc; b++) {
            const float xv = x[(long)b * SD + i];
#pragma unroll
            for (int e = 0; e < Ec; e++) acc[b][e] = fmaf(xv, wv[e], acc[b][e]);
        }
    }

    __shared__ float sm[8][64];
    const int lane = tid & 31, warp = tid >> 5;
#pragma unroll
    for (int b = 0; b < Bc; b++) {
#pragma unroll
        for (int e = 0; e < Ec; e++) {
            float v = acc[b][e];
#pragma unroll
            for (int o = 16; o > 0; o >>= 1) v += __shfl_down_sync(0xffffffffu, v, o);
            if (lane == 0) sm[warp][b * 8 + e] = v;
        }
    }
    __syncthreads();
    if (tid < 64) {
        float s = 0.f;
#pragma unroll
        for (int w2 = 0; w2 < 8; w2++) s += sm[w2][tid];
        g_part[chunk * 64 + tid] = s;
    }
}

__global__ void route_topk_kernel(const float* __restrict__ b_switch) {
    __shared__ float lg[64];
    const int t = threadIdx.x;
    float s = b_switch[t & 7];
    for (int c = 0; c < NCHUNKR; c++) s += g_part[c * 64 + t];
    lg[t] = s;
    __syncthreads();
    if (t < Bc) {
        const float* L = lg + t * 8;
        int i0 = 0; float v0 = L[0];
#pragma unroll
        for (int e = 1; e < 8; e++) if (L[e] > v0) { v0 = L[e]; i0 = e; }
        int i1 = -1; float v1 = -3.0e38f;
#pragma unroll
        for (int e = 0; e < 8; e++) if (e != i0 && L[e] > v1) { v1 = L[e]; i1 = e; }
        g_sel[t * 2 + 0] = i0;
        g_sel[t * 2 + 1] = i1;
    }
}

// ============================================================
// WMMA 3xBF16-split GEMM, in-kernel conversion (R8-proven math),
// now double-buffered BK=16 with register prefetch + clean layouts.
//   A block: 128 rows x [hi16|lo16|pad8] = 40 elems/row (ldm 40)
//   B block: 16 k-rows x [hi128|lo128|pad8] = 264 elems/row (ldm 264, row-major)
//   stage = 128*40 + 16*264 = 9344 elems (18688 B); 2 stages = 37376 B < 48KB
// MODE 0: g_h1  = gelu(x[:, e*128:+128] @ w1[e] + b1[e])   K=128
// MODE 1: g_gsel= gelu(g_h1 @ w2[e] + b2[e])               K=512
// MODE 2: out   = g_gsel @ gather(w_out) + b_out           K=1024
// ============================================================
#define AROWE 40
#define ABLK  (128*AROWE)     // 5120 elems
#define BROWE 264
#define BBLK  (16*BROWE)      // 4224 elems
#define STAGE_E (ABLK + BBLK) // 9344 elems
#define SMEM_B (2*STAGE_E*2)  // 37376 bytes

__device__ __forceinline__ uint32_t pack_bf2(float a, float b) {
    __nv_bfloat162 h; h.x = __float2bfloat16(a); h.y = __float2bfloat16(b);
    return *(uint32_t*)&h;
}

template <int MODE>
__global__ void __launch_bounds__(256)
conv_wmma_gemm(const float* __restrict__ A0, const float* __restrict__ B0,
               const float* __restrict__ bias0, float* __restrict__ outp) {
    extern __shared__ __nv_bfloat16 smem[];

    const int tid = threadIdx.x;
    const int z = blockIdx.z;
    const int rowBlock = blockIdx.y * 128;
    const int colBlock = blockIdx.x * 128;
    const int warp = tid >> 5, lane = tid & 31;
    const int wm = warp & 3, wn = warp >> 2;

    const float* A;
    const float* Bp;
    const float* bias;
    int lda, ldn, akbase, nstages, e0 = 0, e1 = 0;
    if (MODE == 0) {
        const int e = g_sel[z];
        A = A0 + (size_t)(z >> 1) * SD; lda = Dc; akbase = e * SUBD;
        Bp = B0 + (size_t)e * SUBD * SUBH; ldn = SUBH;
        bias = bias0 + e * SUBH;
        nstages = SUBD / 16;
    } else if (MODE == 1) {
        const int e = g_sel[z];
        A = g_h1 + (size_t)z * Sc * SUBH; lda = SUBH; akbase = 0;
        Bp = B0 + (size_t)e * SUBH * SUBH; ldn = SUBH;
        bias = bias0 + e * SUBH;
        nstages = SUBH / 16;
    } else {
        A = g_gsel + (size_t)z * Sc * (2 * SUBH); lda = 2 * SUBH; akbase = 0;
        Bp = B0; ldn = Dc;
        bias = bias0;
        nstages = (2 * SUBH) / 16;
        e0 = g_sel[z * 2]; e1 = g_sel[z * 2 + 1];
    }

    // per-thread load coords (2 float4 each for A and B per chunk)
    const int am0 = tid >> 1,          aks0 = (tid & 1);          // idx j=0: m=tid>>2? see below
    // A: 512 float4 per chunk -> idx = tid + j*256; m = idx>>2, ks = idx&3
    // B: 512 float4 per chunk -> k = idx>>5, ns = idx&31
    (void)am0; (void)aks0;

    wmma::fragment<wmma::accumulator, 16, 16, 16, float> acc[2][4];
#pragma unroll
    for (int mt = 0; mt < 2; mt++)
#pragma unroll
        for (int nt = 0; nt < 4; nt++) wmma::fill_fragment(acc[mt][nt], 0.0f);

    float4 pa[2], pb[2];

    auto loadRegs = [&](int c) {
        const int ak0 = akbase + c * 16;
        const int bk0 = c * 16;
#pragma unroll
        for (int j = 0; j < 2; j++) {
            const int idx = tid + j * 256;
            const int m = idx >> 2, ks = idx & 3;
            pa[j] = *(const float4*)(A + (size_t)(rowBlock + m) * lda + ak0 + ks * 4);
            const int k = idx >> 5, ns = idx & 31;
            const int kg = bk0 + k;
            const float* brow;
            if (MODE == 2) {
                const int r = (kg < SUBH) ? (e0 * SUBH + kg) : (e1 * SUBH + kg - SUBH);
                brow = Bp + (size_t)r * Dc;
            } else {
                brow = Bp + (size_t)kg * ldn;
            }
            pb[j] = *(const float4*)(brow + colBlock + ns * 4);
        }
    };

    auto convStore = [&](int st) {
        __nv_bfloat16* s = smem + st * STAGE_E;
#pragma unroll
        for (int j = 0; j < 2; j++) {
            {   // A
                const int idx = tid + j * 256;
                const int m = idx >> 2, ks = idx & 3;
                const float4 v = pa[j];
                const float hx = __bfloat162float(__float2bfloat16(v.x));
                const float hy = __bfloat162float(__float2bfloat16(v.y));
                const float hz = __bfloat162float(__float2bfloat16(v.z));
                const float hw = __bfloat162float(__float2bfloat16(v.w));
                uint2 hi, lo;
                hi.x = pack_bf2(v.x, v.y);       hi.y = pack_bf2(v.z, v.w);
                lo.x = pack_bf2(v.x - hx, v.y - hy); lo.y = pack_bf2(v.z - hz, v.w - hw);
                *(uint2*)(s + m * AROWE + ks * 4)      = hi;
                *(uint2*)(s + m * AROWE + 16 + ks * 4) = lo;
            }
            {   // B
                const int idx = tid + j * 256;
                const int k = idx >> 5, ns = idx & 31;
                const float4 v = pb[j];
                const float hx = __bfloat162float(__float2bfloat16(v.x));
                const float hy = __bfloat162float(__float2bfloat16(v.y));
                const float hz = __bfloat162float(__float2bfloat16(v.z));
                const float hw = __bfloat162float(__float2bfloat16(v.w));
                uint2 hi, lo;
                hi.x = pack_bf2(v.x, v.y);       hi.y = pack_bf2(v.z, v.w);
                lo.x = pack_bf2(v.x - hx, v.y - hy); lo.y = pack_bf2(v.z - hz, v.w - hw);
                __nv_bfloat16* bbase = s + ABLK + k * BROWE + ns * 4;
                *(uint2*)(bbase)       = hi;
                *(uint2*)(bbase + 128) = lo;
            }
        }
    };

    // prologue: fill stage 0
    loadRegs(0);
    convStore(0);
    __syncthreads();

    for (int c = 0; c < nstages; c++) {
        if (c + 1 < nstages) loadRegs(c + 1);   // issue global loads early

        // ---- compute chunk c from stage c&1 ----
        const __nv_bfloat16* s = smem + (c & 1) * STAGE_E;
        wmma::fragment<wmma::matrix_a, 16, 16, 16, __nv_bfloat16, wmma::row_major> ah[2], al[2];
#pragma unroll
        for (int mt = 0; mt < 2; mt++) {
            const __nv_bfloat16* ab = s + (wm * 32 + mt * 16) * AROWE;
            wmma::load_matrix_sync(ah[mt], ab, AROWE);
            wmma::load_matrix_sync(al[mt], ab + 16, AROWE);
        }
#pragma unroll
        for (int nt = 0; nt < 4; nt++) {
            wmma::fragment<wmma::matrix_b, 16, 16, 16, __nv_bfloat16, wmma::row_major> bh, bl;
            const __nv_bfloat16* bb = s + ABLK + (wn * 64 + nt * 16);
            wmma::load_matrix_sync(bh, bb, BROWE);
            wmma::load_matrix_sync(bl, bb + 128, BROWE);
#pragma unroll
            for (int mt = 0; mt < 2; mt++) {
                wmma::mma_sync(acc[mt][nt], ah[mt], bh, acc[mt][nt]);
                wmma::mma_sync(acc[mt][nt], ah[mt], bl, acc[mt][nt]);
                wmma::mma_sync(acc[mt][nt], al[mt], bh, acc[mt][nt]);
            }
        }

        if (c + 1 < nstages) convStore((c + 1) & 1);  // fill other stage
        __syncthreads();
    }

    // ---- epilogue (R8-proven): frags -> smem scratch -> transform -> write ----
    float* scr = (float*)smem + warp * (16 * 68);
    const int srow = lane >> 1;
    const int cb = (lane & 1) * 32;

#pragma unroll
    for (int mt = 0; mt < 2; mt++) {
#pragma unroll
        for (int nt = 0; nt < 4; nt++)
            wmma::store_matrix_sync(scr + nt * 16, acc[mt][nt], 68, wmma::mem_row_major);
        __syncwarp();

        const int grow = rowBlock + wm * 32 + mt * 16 + srow;
        const int gcol0 = colBlock + wn * 64 + cb;

        if (MODE == 2) {
            float* orow = outp + (size_t)(z * Sc + grow) * Dc + gcol0;
#pragma unroll
            for (int cc = 0; cc < 32; cc += 2) {
                const float v0 = scr[srow * 68 + cb + cc]     + bias[gcol0 + cc];
                const float v1 = scr[srow * 68 + cb + cc + 1] + bias[gcol0 + cc + 1];
                *(float2*)(orow + cc) = make_float2(v0, v1);
            }
        } else {
            float* dst;
            if (MODE == 0) {
                dst = g_h1 + (size_t)(z * Sc + grow) * SUBH + gcol0;
            } else {
                dst = g_gsel + (size_t)((z >> 1) * Sc + grow) * (2 * SUBH)
                    + (z & 1) * SUBH + gcol0;
            }
#pragma unroll
            for (int cc = 0; cc < 32; cc += 2) {
                const float g0 = gelu_exact(scr[srow * 68 + cb + cc]     + bias[gcol0 + cc]);
                const float g1 = gelu_exact(scr[srow * 68 + cb + cc + 1] + bias[gcol0 + cc + 1]);
                *(float2*)(dst + cc) = make_float2(g0, g1);
            }
        }
        __syncwarp();
    }
}

// ============================================================
extern "C" void kernel_launch(void* const* d_in, const int* in_sizes, int n_in,
                              void* d_out, int out_size) {
    const float* x        = (const float*)d_in[0];
    const float* w_switch = (const float*)d_in[1];
    const float* b_switch = (const float*)d_in[2];
    const float* w1       = (const float*)d_in[3];
    const float* b1       = (const float*)d_in[4];
    const float* w2       = (const float*)d_in[5];
    const float* b2       = (const float*)d_in[6];
    const float* w_out    = (const float*)d_in[7];
    const float* b_out    = (const float*)d_in[8];
    float* out = (float*)d_out;

    // 1) routing (proven)
    route_partial_kernel<<<NCHUNKR, 256>>>(x, w_switch);
    route_topk_kernel<<<1, 64>>>(b_switch);

    // 2) WMMA expert MLP, double-buffered, in-kernel conversion
    conv_wmma_gemm<0><<<dim3(SUBH / 128, Sc / 128, 16), 256, SMEM_B>>>(x, w1, b1, nullptr);
    conv_wmma_gemm<1><<<dim3(SUBH / 128, Sc / 128, 16), 256, SMEM_B>>>(nullptr, w2, b2, nullptr);
    conv_wmma_gemm<2><<<dim3(Dc / 128, Sc / 128, Bc), 256, SMEM_B>>>(nullptr, w_out, b_out, out);
}

// round 10
// speedup vs baseline: 3.1765x; 1.5685x over previous
#include <cuda_runtime.h>
#include <cuda_fp16.h>
#include <mma.h>
#include <math.h>
#include <stdint.h>

using namespace nvcuda;

#define Bc 8
#define Sc 2048
#define Dc 1024
#define Ec 8
#define SUBD 128
#define SUBH 512
#define SD (Sc*Dc)
#define NCHUNKR 256
#define CHUNKR (SD/NCHUNKR)

// ---------------- scratch (static device globals) ----------------
__device__ float g_h1[16*Sc*SUBH];
__device__ float g_gsel[(long)Bc*Sc*2*SUBH];
__device__ float g_part[NCHUNKR*Bc*Ec];
__device__ int   g_sel[Bc*2];

__device__ __forceinline__ float gelu_exact(float v) {
    return 0.5f * v * (1.0f + erff(v * 0.70710678118654752440f));
}

// ============================================================
// Routing (R1 verbatim — proven)
// ============================================================
__global__ void route_partial_kernel(const float* __restrict__ x,
                                     const float* __restrict__ w) {
    const int chunk = blockIdx.x;
    const int tid   = threadIdx.x;

    float acc[Bc][Ec];
#pragma unroll
    for (int b = 0; b < Bc; b++)
#pragma unroll
        for (int e = 0; e < Ec; e++) acc[b][e] = 0.f;

    const long base = (long)chunk * CHUNKR;
    for (int it = 0; it < CHUNKR / 256; it++) {
        const long i = base + it * 256 + tid;
        const float4 w0 = *(const float4*)(w + i * 8);
        const float4 w1v = *(const float4*)(w + i * 8 + 4);
        const float wv[8] = {w0.x, w0.y, w0.z, w0.w, w1v.x, w1v.y, w1v.z, w1v.w};
#pragma unroll
        for (int b = 0; b < Bc; b++) {
            const float xv = x[(long)b * SD + i];
#pragma unroll
            for (int e = 0; e < Ec; e++) acc[b][e] = fmaf(xv, wv[e], acc[b][e]);
        }
    }

    __shared__ float sm[8][64];
    const int lane = tid & 31, warp = tid >> 5;
#pragma unroll
    for (int b = 0; b < Bc; b++) {
#pragma unroll
        for (int e = 0; e < Ec; e++) {
            float v = acc[b][e];
#pragma unroll
            for (int o = 16; o > 0; o >>= 1) v += __shfl_down_sync(0xffffffffu, v, o);
            if (lane == 0) sm[warp][b * 8 + e] = v;
        }
    }
    __syncthreads();
    if (tid < 64) {
        float s = 0.f;
#pragma unroll
        for (int w2 = 0; w2 < 8; w2++) s += sm[w2][tid];
        g_part[chunk * 64 + tid] = s;
    }
}

__global__ void route_topk_kernel(const float* __restrict__ b_switch) {
    __shared__ float lg[64];
    const int t = threadIdx.x;
    float s = b_switch[t & 7];
    for (int c = 0; c < NCHUNKR; c++) s += g_part[c * 64 + t];
    lg[t] = s;
    __syncthreads();
    if (t < Bc) {
        const float* L = lg + t * 8;
        int i0 = 0; float v0 = L[0];
#pragma unroll
        for (int e = 1; e < 8; e++) if (L[e] > v0) { v0 = L[e]; i0 = e; }
        int i1 = -1; float v1 = -3.0e38f;
#pragma unroll
        for (int e = 0; e < 8; e++) if (e != i0 && L[e] > v1) { v1 = L[e]; i1 = e; }
        g_sel[t * 2 + 0] = i0;
        g_sel[t * 2 + 1] = i1;
    }
}

// ============================================================
// WMMA fp16 2-term split GEMM (A = Ah+Al fp16 pair, B = single fp16),
// in-kernel conversion, double-buffered BK=16, register prefetch.
//   A block: 128 rows x [hi16|lo16|pad8] = 40 halfs/row (80B; banks 20r%32 distinct)
//   B block: 16 k-rows x [128 halfs|pad8] = 136 halfs/row (272B; banks 4r%32 distinct)
//   stage = 128*40 + 16*136 = 7296 halfs (14592B); 2 stages = 29184B
//   smem alloc = max(2 stages, epilogue scratch 8*16*68*4 = 34816B) = 34816B < 48KB
// MODE 0: g_h1  = gelu(x[:, e*128:+128] @ w1[e] + b1[e])   K=128
// MODE 1: g_gsel= gelu(g_h1 @ w2[e] + b2[e])               K=512
// MODE 2: out   = g_gsel @ gather(w_out) + b_out           K=1024
// ============================================================
#define AROWE 40
#define ABLK  (128*AROWE)     // 5120 halfs
#define BROWE 136
#define BBLK  (16*BROWE)      // 2176 halfs
#define STAGE_E (ABLK + BBLK) // 7296 halfs
#define SMEM_ALLOC 34816      // bytes (epilogue scratch dominates)

__device__ __forceinline__ uint32_t pack_h2(float a, float b) {
    __half2 h; h.x = __float2half_rn(a); h.y = __float2half_rn(b);
    return *(uint32_t*)&h;
}

template <int MODE>
__global__ void __launch_bounds__(256)
conv_wmma_gemm(const float* __restrict__ A0, const float* __restrict__ B0,
               const float* __restrict__ bias0, float* __restrict__ outp) {
    extern __shared__ __half smem[];

    const int tid = threadIdx.x;
    const int z = blockIdx.z;
    const int rowBlock = blockIdx.y * 128;
    const int colBlock = blockIdx.x * 128;
    const int warp = tid >> 5, lane = tid & 31;
    const int wm = warp & 3, wn = warp >> 2;

    const float* A;
    const float* Bp;
    const float* bias;
    int lda, ldn, akbase, nstages, e0 = 0, e1 = 0;
    if (MODE == 0) {
        const int e = g_sel[z];
        A = A0 + (size_t)(z >> 1) * SD; lda = Dc; akbase = e * SUBD;
        Bp = B0 + (size_t)e * SUBD * SUBH; ldn = SUBH;
        bias = bias0 + e * SUBH;
        nstages = SUBD / 16;
    } else if (MODE == 1) {
        const int e = g_sel[z];
        A = g_h1 + (size_t)z * Sc * SUBH; lda = SUBH; akbase = 0;
        Bp = B0 + (size_t)e * SUBH * SUBH; ldn = SUBH;
        bias = bias0 + e * SUBH;
        nstages = SUBH / 16;
    } else {
        A = g_gsel + (size_t)z * Sc * (2 * SUBH); lda = 2 * SUBH; akbase = 0;
        Bp = B0; ldn = Dc;
        bias = bias0;
        nstages = (2 * SUBH) / 16;
        e0 = g_sel[z * 2]; e1 = g_sel[z * 2 + 1];
    }

    wmma::fragment<wmma::accumulator, 16, 16, 16, float> acc[2][4];
#pragma unroll
    for (int mt = 0; mt < 2; mt++)
#pragma unroll
        for (int nt = 0; nt < 4; nt++) wmma::fill_fragment(acc[mt][nt], 0.0f);

    float4 pa[2], pb[2];

    auto loadRegs = [&](int c) {
        const int ak0 = akbase + c * 16;
        const int bk0 = c * 16;
#pragma unroll
        for (int j = 0; j < 2; j++) {
            const int idx = tid + j * 256;
            const int m = idx >> 2, ks = idx & 3;
            pa[j] = *(const float4*)(A + (size_t)(rowBlock + m) * lda + ak0 + ks * 4);
            const int k = idx >> 5, ns = idx & 31;
            const int kg = bk0 + k;
            const float* brow;
            if (MODE == 2) {
                const int r = (kg < SUBH) ? (e0 * SUBH + kg) : (e1 * SUBH + kg - SUBH);
                brow = Bp + (size_t)r * Dc;
            } else {
                brow = Bp + (size_t)kg * ldn;
            }
            pb[j] = *(const float4*)(brow + colBlock + ns * 4);
        }
    };

    auto convStore = [&](int st) {
        __half* s = smem + st * STAGE_E;
#pragma unroll
        for (int j = 0; j < 2; j++) {
            {   // A: fp16 hi + residual lo
                const int idx = tid + j * 256;
                const int m = idx >> 2, ks = idx & 3;
                const float4 v = pa[j];
                const float hx = __half2float(__float2half_rn(v.x));
                const float hy = __half2float(__float2half_rn(v.y));
                const float hz = __half2float(__float2half_rn(v.z));
                const float hw = __half2float(__float2half_rn(v.w));
                uint2 hi, lo;
                hi.x = pack_h2(v.x, v.y);           hi.y = pack_h2(v.z, v.w);
                lo.x = pack_h2(v.x - hx, v.y - hy); lo.y = pack_h2(v.z - hz, v.w - hw);
                *(uint2*)(s + m * AROWE + ks * 4)      = hi;
                *(uint2*)(s + m * AROWE + 16 + ks * 4) = lo;
            }
            {   // B: single fp16
                const int idx = tid + j * 256;
                const int k = idx >> 5, ns = idx & 31;
                const float4 v = pb[j];
                uint2 hv;
                hv.x = pack_h2(v.x, v.y); hv.y = pack_h2(v.z, v.w);
                *(uint2*)(s + ABLK + k * BROWE + ns * 4) = hv;
            }
        }
    };

    // prologue: fill stage 0
    loadRegs(0);
    convStore(0);
    __syncthreads();

    for (int c = 0; c < nstages; c++) {
        if (c + 1 < nstages) loadRegs(c + 1);   // issue next global loads early

        // ---- compute chunk c from stage c&1 ----
        const __half* s = smem + (c & 1) * STAGE_E;
        wmma::fragment<wmma::matrix_a, 16, 16, 16, __half, wmma::row_major> ah[2], al[2];
#pragma unroll
        for (int mt = 0; mt < 2; mt++) {
            const __half* ab = s + (wm * 32 + mt * 16) * AROWE;
            wmma::load_matrix_sync(ah[mt], ab, AROWE);
            wmma::load_matrix_sync(al[mt], ab + 16, AROWE);
        }
#pragma unroll
        for (int nt = 0; nt < 4; nt++) {
            wmma::fragment<wmma::matrix_b, 16, 16, 16, __half, wmma::row_major> bf;
            wmma::load_matrix_sync(bf, s + ABLK + (wn * 64 + nt * 16), BROWE);
#pragma unroll
            for (int mt = 0; mt < 2; mt++) {
                wmma::mma_sync(acc[mt][nt], ah[mt], bf, acc[mt][nt]);
                wmma::mma_sync(acc[mt][nt], al[mt], bf, acc[mt][nt]);
            }
        }

        if (c + 1 < nstages) convStore((c + 1) & 1);
        __syncthreads();
    }

    // ---- epilogue (R8/R9-proven): frags -> smem scratch -> transform -> write ----
    float* scr = (float*)smem + warp * (16 * 68);
    const int srow = lane >> 1;
    const int cb = (lane & 1) * 32;

#pragma unroll
    for (int mt = 0; mt < 2; mt++) {
#pragma unroll
        for (int nt = 0; nt < 4; nt++)
            wmma::store_matrix_sync(scr + nt * 16, acc[mt][nt], 68, wmma::mem_row_major);
        __syncwarp();

        const int grow = rowBlock + wm * 32 + mt * 16 + srow;
        const int gcol0 = colBlock + wn * 64 + cb;

        if (MODE == 2) {
            float* orow = outp + (size_t)(z * Sc + grow) * Dc + gcol0;
#pragma unroll
            for (int cc = 0; cc < 32; cc += 2) {
                const float v0 = scr[srow * 68 + cb + cc]     + bias[gcol0 + cc];
                const float v1 = scr[srow * 68 + cb + cc + 1] + bias[gcol0 + cc + 1];
                *(float2*)(orow + cc) = make_float2(v0, v1);
            }
        } else {
            float* dst;
            if (MODE == 0) {
                dst = g_h1 + (size_t)(z * Sc + grow) * SUBH + gcol0;
            } else {
                dst = g_gsel + (size_t)((z >> 1) * Sc + grow) * (2 * SUBH)
                    + (z & 1) * SUBH + gcol0;
            }
#pragma unroll
            for (int cc = 0; cc < 32; cc += 2) {
                const float g0 = gelu_exact(scr[srow * 68 + cb + cc]     + bias[gcol0 + cc]);
                const float g1 = gelu_exact(scr[srow * 68 + cb + cc + 1] + bias[gcol0 + cc + 1]);
                *(float2*)(dst + cc) = make_float2(g0, g1);
            }
        }
        __syncwarp();
    }
}

// ============================================================
extern "C" void kernel_launch(void* const* d_in, const int* in_sizes, int n_in,
                              void* d_out, int out_size) {
    const float* x        = (const float*)d_in[0];
    const float* w_switch = (const float*)d_in[1];
    const float* b_switch = (const float*)d_in[2];
    const float* w1       = (const float*)d_in[3];
    const float* b1       = (const float*)d_in[4];
    const float* w2       = (const float*)d_in[5];
    const float* b2       = (const float*)d_in[6];
    const float* w_out    = (const float*)d_in[7];
    const float* b_out    = (const float*)d_in[8];
    float* out = (float*)d_out;

    // 1) routing (proven)
    route_partial_kernel<<<NCHUNKR, 256>>>(x, w_switch);
    route_topk_kernel<<<1, 64>>>(b_switch);

    // 2) fp16 2-term WMMA expert MLP, double-buffered, in-kernel conversion
    conv_wmma_gemm<0><<<dim3(SUBH / 128, Sc / 128, 16), 256, SMEM_ALLOC>>>(x, w1, b1, nullptr);
    conv_wmma_gemm<1><<<dim3(SUBH / 128, Sc / 128, 16), 256, SMEM_ALLOC>>>(nullptr, w2, b2, nullptr);
    conv_wmma_gemm<2><<<dim3(Dc / 128, Sc / 128, Bc), 256, SMEM_ALLOC>>>(nullptr, w_out, b_out, out);
}